// round 12
// baseline (speedup 1.0000x reference)
#include <cuda_runtime.h>
#include <cuda_bf16.h>

#define BATCH 128
#define TSTEPS 1024
#define IDIM 256
#define HDIM 512
#define GDIM 2048
#define REC_CHUNK 128

typedef unsigned long long ull;

// ------------------------------- scratch ----------------------------------
__device__ float g_xw[(size_t)TSTEPS * BATCH * GDIM];   // [t][b][g'] (1 GiB)
__device__ float g_Wsm[128 * 512 * 16];                 // [cta][j][kl][gate]
__device__ float g_Wih_t[IDIM * GDIM];                  // [i][g']
__device__ float g_bias[GDIM];                          // reordered b_ih+b_hh
__device__ float g_h[2 * BATCH * HDIM];                 // double-buffered h
__device__ float g_c[BATCH * HDIM];                     // persistent c between chunks
__device__ unsigned g_bar;

// ----------------------------- f32x2 helpers ------------------------------
__device__ __forceinline__ ull pk2(float lo, float hi) {
    ull r; asm("mov.b64 %0, {%1, %2};" : "=l"(r) : "f"(lo), "f"(hi)); return r;
}
__device__ __forceinline__ void fma2(ull& d, ull a, ull b) {
    asm("fma.rn.f32x2 %0, %1, %2, %0;" : "+l"(d) : "l"(a), "l"(b));
}
__device__ __forceinline__ float2 upk2(ull v) {
    float2 r; asm("mov.b64 {%0, %1}, %2;" : "=f"(r.x), "=f"(r.y) : "l"(v)); return r;
}

// ------------------------------ init kernel -------------------------------
// Column reorder: g' = 16*cta + 4*kl + gate, khid = 4*cta + kl.
__global__ void init_kernel(const float* __restrict__ W_ih,
                            const float* __restrict__ W_hh,
                            const float* __restrict__ b_ih,
                            const float* __restrict__ b_hh) {
    int idx = blockIdx.x * blockDim.x + threadIdx.x;
    int stride = gridDim.x * blockDim.x;

    // g_Wsm[cta][j][kl][gate] = W_hh[gate*512 + cta*4 + kl][j]
    for (int p = idx; p < 128 * 512 * 16; p += stride) {
        int cta  = p >> 13;
        int r    = p & 8191;
        int j    = r >> 4;
        int kl   = (r >> 2) & 3;
        int gate = r & 3;
        g_Wsm[p] = W_hh[(size_t)(gate * 512 + cta * 4 + kl) * 512 + j];
    }
    for (int p = idx; p < IDIM * GDIM; p += stride) {
        int i = p >> 11, g = p & 2047;
        int gate = g & 3, kl = (g >> 2) & 3, khid = ((g >> 4) << 2) + kl;
        g_Wih_t[p] = W_ih[(size_t)(gate * 512 + khid) * 256 + i];
    }
    for (int p = idx; p < GDIM; p += stride) {
        int gate = p & 3, kl = (p >> 2) & 3, khid = ((p >> 4) << 2) + kl;
        g_bias[p] = b_ih[gate * 512 + khid] + b_hh[gate * 512 + khid];
    }
    if (idx == 0) g_bar = 0u;
}

// ------------------------------- xW GEMM ----------------------------------
#define GM_BK 32
#define AS_STRIDE 68

__global__ __launch_bounds__(256) void xw_gemm(const float* __restrict__ x) {
    __shared__ float As[GM_BK * AS_STRIDE];   // [k][row], 64 rows
    __shared__ float Bs[GM_BK * 128];         // [k][n]

    const int by = blockIdx.y;
    const int t  = by >> 1;
    const int b0 = (by & 1) * 64;
    const int n0 = blockIdx.x * 128;
    const int tid = threadIdx.x;
    const int tm = tid & 15;
    const int tn8 = (tid >> 4) * 8;

    const float* xbase = x + ((size_t)b0 * TSTEPS + t) * IDIM;

    float acc[4][8];
    #pragma unroll
    for (int m = 0; m < 4; m++)
        #pragma unroll
        for (int n = 0; n < 8; n++) acc[m][n] = 0.0f;

    for (int k0 = 0; k0 < IDIM; k0 += GM_BK) {
        #pragma unroll
        for (int l = 0; l < 2; l++) {
            int idx4 = tid + l * 256;
            int k4 = (idx4 & 7) * 4;
            int row = idx4 >> 3;
            float4 v = *(const float4*)(xbase + (size_t)row * (TSTEPS * IDIM) + k0 + k4);
            As[(k4 + 0) * AS_STRIDE + row] = v.x;
            As[(k4 + 1) * AS_STRIDE + row] = v.y;
            As[(k4 + 2) * AS_STRIDE + row] = v.z;
            As[(k4 + 3) * AS_STRIDE + row] = v.w;
        }
        #pragma unroll
        for (int l = 0; l < 4; l++) {
            int idx4 = tid + l * 256;
            int n4 = (idx4 & 31) * 4;
            int k  = idx4 >> 5;
            *(float4*)(&Bs[k * 128 + n4]) =
                *(const float4*)(g_Wih_t + (size_t)(k0 + k) * GDIM + n0 + n4);
        }
        __syncthreads();

        #pragma unroll
        for (int k = 0; k < GM_BK; k++) {
            float4 a  = *(const float4*)(&As[k * AS_STRIDE + tm * 4]);
            float4 b0v = *(const float4*)(&Bs[k * 128 + tn8]);
            float4 b1v = *(const float4*)(&Bs[k * 128 + tn8 + 4]);
            float av[4] = {a.x, a.y, a.z, a.w};
            float bv[8] = {b0v.x, b0v.y, b0v.z, b0v.w, b1v.x, b1v.y, b1v.z, b1v.w};
            #pragma unroll
            for (int m = 0; m < 4; m++)
                #pragma unroll
                for (int n = 0; n < 8; n++)
                    acc[m][n] = fmaf(av[m], bv[n], acc[m][n]);
        }
        __syncthreads();
    }

    float4 bz0 = *(const float4*)(g_bias + n0 + tn8);
    float4 bz1 = *(const float4*)(g_bias + n0 + tn8 + 4);
    #pragma unroll
    for (int m = 0; m < 4; m++) {
        int brow = b0 + tm * 4 + m;
        float* op = g_xw + ((size_t)t * BATCH + brow) * GDIM + n0 + tn8;
        *(float4*)op = make_float4(acc[m][0] + bz0.x, acc[m][1] + bz0.y,
                                   acc[m][2] + bz0.z, acc[m][3] + bz0.w);
        *(float4*)(op + 4) = make_float4(acc[m][4] + bz1.x, acc[m][5] + bz1.y,
                                         acc[m][6] + bz1.z, acc[m][7] + bz1.w);
    }
}

// ---------------------------- recurrent kernel ----------------------------
// Quad (4 threads, same b) cooperatively loads h: lane kl owns 4 of each 16-j
// block; values broadcast via width-4 shuffles. W read as (i,f,g,o) float4 per
// j from smem; gates accumulated in packed f32x2 pairs (I,F) / (G,O).

// Consume the 4 j's owned by quad lane SRC within the current 16-j block.
#define QSTEP(SRC) {                                                       \
    float hx = __shfl_sync(0xffffffffu, mine.x, (SRC), 4);                 \
    float hy = __shfl_sync(0xffffffffu, mine.y, (SRC), 4);                 \
    float hz = __shfl_sync(0xffffffffu, mine.z, (SRC), 4);                 \
    float hw = __shfl_sync(0xffffffffu, mine.w, (SRC), 4);                 \
    const float* wp = wb + (SRC) * 64;                                     \
    ulonglong2 w0 = *(const ulonglong2*)(wp);                              \
    ulonglong2 w1 = *(const ulonglong2*)(wp + 16);                         \
    ulonglong2 w2 = *(const ulonglong2*)(wp + 32);                         \
    ulonglong2 w3 = *(const ulonglong2*)(wp + 48);                         \
    ull h2;                                                                \
    h2 = pk2(hx, hx); fma2(aIF, h2, w0.x); fma2(aGO, h2, w0.y);            \
    h2 = pk2(hy, hy); fma2(aIF, h2, w1.x); fma2(aGO, h2, w1.y);            \
    h2 = pk2(hz, hz); fma2(aIF, h2, w2.x); fma2(aGO, h2, w2.y);            \
    h2 = pk2(hw, hw); fma2(aIF, h2, w3.x); fma2(aGO, h2, w3.y);            \
}

__global__ __launch_bounds__(512, 1) void lstm_rec(int t0) {
    __shared__ float sW[512 * 16];   // 32 KB: [j][kl][gate]

    const int cta = blockIdx.x;    // 0..127
    const int tid = threadIdx.x;   // 0..511

    {   // stage this CTA's W_hh slice (constant over all steps)
        const float* wsrc = g_Wsm + (size_t)cta * 8192;
        #pragma unroll
        for (int p = tid; p < 8192; p += 512) sW[p] = wsrc[p];
    }
    __syncthreads();

    const int kl  = tid & 3;
    const int b   = tid >> 2;
    const int kl4 = kl * 4;
    const int hoff = b * HDIM;
    const int cell = hoff + cta * 4 + kl;
    const float* xwp = g_xw + (size_t)b * GDIM + cta * 16 + kl4;
    float* hout_base = g_h + cell;

    float creg = (t0 == 0) ? 0.0f : g_c[cell];

    float4 xv = *(const float4*)(xwp + (size_t)t0 * (BATCH * GDIM));
    float4 xv_next;

    for (int tl = 0; tl < REC_CHUNK; tl++) {
        const int t = t0 + tl;
        ull aIF = 0ull, aGO = 0ull;

        if (t > 0) {
            const float* hrow = g_h + (size_t)(t & 1) * (BATCH * HDIM) + hoff;
            float4 mine = __ldcg((const float4*)(hrow + kl4));
            #pragma unroll 1
            for (int blk = 0; blk < 32; blk++) {
                float4 nxt;
                if (blk + 1 < 32)
                    nxt = __ldcg((const float4*)(hrow + (blk + 1) * 16 + kl4));
                const float* wb = sW + blk * 256 + kl4;   // 16 j * 16 floats
                QSTEP(0) QSTEP(1) QSTEP(2) QSTEP(3)
                mine = nxt;
            }
        }

        float2 rIF = upk2(aIF), rGO = upk2(aGO);
        float pi = xv.x + rIF.x;
        float pf = xv.y + rIF.y;
        float pg = xv.z + rGO.x;
        float po = xv.w + rGO.y;

        float ig = __fdividef(1.0f, 1.0f + __expf(-pi));
        float fg = __fdividef(1.0f, 1.0f + __expf(-pf));
        float gg = 1.0f - __fdividef(2.0f, __expf(2.0f * pg) + 1.0f);
        float og = __fdividef(1.0f, 1.0f + __expf(-po));

        creg = fg * creg + ig * gg;
        float th = 1.0f - __fdividef(2.0f, __expf(2.0f * creg) + 1.0f);
        float hv = og * th;

        float* hp = hout_base + (size_t)((t + 1) & 1) * (BATCH * HDIM);
        asm volatile("st.global.cg.f32 [%0], %1;" :: "l"(hp), "f"(hv) : "memory");

        // prefetch next step's x-projection (constant data; overlaps barrier)
        if (tl + 1 < REC_CHUNK)
            xv_next = *(const float4*)(xwp + (size_t)(t + 1) * (BATCH * GDIM));

        // ---- grid barrier (128 CTAs, all resident) ----
        unsigned bar_t = (unsigned)(t + 1) * 128u;
        __syncthreads();
        if (tid == 0) {
            asm volatile("red.release.gpu.global.add.u32 [%0], 1;"
                         :: "l"(&g_bar) : "memory");
            unsigned v;
            do {
                asm volatile("ld.acquire.gpu.global.u32 %0, [%1];"
                             : "=r"(v) : "l"(&g_bar) : "memory");
            } while (v < bar_t);
        }
        __syncthreads();

        xv = xv_next;
    }

    g_c[cell] = creg;
}

// ------------------------------- fc kernel --------------------------------
__global__ void fc_kernel(const float* __restrict__ fc_w,
                          const float* __restrict__ fc_b,
                          float* __restrict__ out) {
    int b = blockIdx.x;          // 128 blocks
    int tid = threadIdx.x;       // 128 threads
    const float* h = g_h + (size_t)b * HDIM;   // final h lives in buffer 0
    float s = 0.0f;
    #pragma unroll
    for (int j = tid; j < HDIM; j += 128) s = fmaf(h[j], fc_w[j], s);
    s += __shfl_down_sync(0xffffffffu, s, 16);
    s += __shfl_down_sync(0xffffffffu, s, 8);
    s += __shfl_down_sync(0xffffffffu, s, 4);
    s += __shfl_down_sync(0xffffffffu, s, 2);
    s += __shfl_down_sync(0xffffffffu, s, 1);
    __shared__ float red[4];
    if ((tid & 31) == 0) red[tid >> 5] = s;
    __syncthreads();
    if (tid == 0) out[b] = red[0] + red[1] + red[2] + red[3] + fc_b[0];
}

// ------------------------------- launcher ---------------------------------
extern "C" void kernel_launch(void* const* d_in, const int* in_sizes, int n_in,
                              void* d_out, int out_size) {
    const float* x    = (const float*)d_in[0];
    const float* W_ih = (const float*)d_in[1];
    const float* W_hh = (const float*)d_in[2];
    const float* b_ih = (const float*)d_in[3];
    const float* b_hh = (const float*)d_in[4];
    const float* fc_w = (const float*)d_in[5];
    const float* fc_b = (const float*)d_in[6];
    float* out = (float*)d_out;

    init_kernel<<<2048, 256>>>(W_ih, W_hh, b_ih, b_hh);
    dim3 gg(16, 2048);
    xw_gemm<<<gg, 256>>>(x);
    for (int c = 0; c < TSTEPS / REC_CHUNK; c++)
        lstm_rec<<<128, 512>>>(c * REC_CHUNK);
    fc_kernel<<<128, 128>>>(fc_w, fc_b, out);
}

// round 13
// speedup vs baseline: 2.1219x; 2.1219x over previous
#include <cuda_runtime.h>

#define BATCH 128
#define TSTEPS 1024
#define IDIM 256
#define HDIM 512
#define GDIM 2048
#define REC_CHUNK 128
#define HB (HDIM * BATCH)
typedef unsigned long long ull;

__device__ float g_xw[(size_t)TSTEPS * GDIM * BATCH];  // [t][g'][b]
__device__ float g_W2[128 * 512 * 4 * 8];              // [cta][j][khid][gate*(w,w)]
__device__ float g_Wih_t[IDIM * GDIM];                 // [i][g']
__device__ float g_bias[GDIM];
__device__ float g_hP[2 * HB];                         // [buf][j][b]
__device__ float g_c[BATCH * HDIM];
__device__ unsigned g_bar;

__device__ __forceinline__ void fma2(ull& d, ull a, ull b) {
    asm("fma.rn.f32x2 %0, %1, %2, %0;" : "+l"(d) : "l"(a), "l"(b));
}

// ------------------------------ init --------------------------------------
// g' = 16*cta + 4*kl + gate ; khid_global = 4*cta + kl
__global__ void init_kernel(const float* __restrict__ W_ih,
                            const float* __restrict__ W_hh,
                            const float* __restrict__ b_ih,
                            const float* __restrict__ b_hh) {
    int idx = blockIdx.x * blockDim.x + threadIdx.x;
    int stride = gridDim.x * blockDim.x;
    for (int p = idx; p < 128 * 512 * 16; p += stride) {
        int cta = p >> 13, r = p & 8191;
        int j = r >> 4, kl = (r >> 2) & 3, gate = r & 3;
        float v = W_hh[(size_t)(gate * 512 + cta * 4 + kl) * 512 + j];
        g_W2[(size_t)p * 2] = v;
        g_W2[(size_t)p * 2 + 1] = v;
    }
    for (int p = idx; p < IDIM * GDIM; p += stride) {
        int i = p >> 11, g = p & 2047;
        int gate = g & 3, kl = (g >> 2) & 3, khid = ((g >> 4) << 2) + kl;
        g_Wih_t[p] = W_ih[(size_t)(gate * 512 + khid) * 256 + i];
    }
    for (int p = idx; p < GDIM; p += stride) {
        int gate = p & 3, kl = (p >> 2) & 3, khid = ((p >> 4) << 2) + kl;
        g_bias[p] = b_ih[gate * 512 + khid] + b_hh[gate * 512 + khid];
    }
    if (idx == 0) g_bar = 0u;
}

// ----------------------------- xW GEMM ------------------------------------
#define GM_BK 32
#define AS_STRIDE 68
__global__ __launch_bounds__(256) void xw_gemm(const float* __restrict__ x) {
    __shared__ float As[GM_BK * AS_STRIDE];
    __shared__ float Bs[GM_BK * 128];
    const int by = blockIdx.y;
    const int t = by >> 1, b0 = (by & 1) * 64;
    const int n0 = blockIdx.x * 128;
    const int tid = threadIdx.x;
    const int tm = tid & 15, tn8 = (tid >> 4) * 8;
    const float* xbase = x + ((size_t)b0 * TSTEPS + t) * IDIM;

    float acc[4][8];
    #pragma unroll
    for (int m = 0; m < 4; m++)
        #pragma unroll
        for (int n = 0; n < 8; n++) acc[m][n] = 0.0f;

    for (int k0 = 0; k0 < IDIM; k0 += GM_BK) {
        #pragma unroll
        for (int l = 0; l < 2; l++) {
            int idx4 = tid + l * 256;
            int k4 = (idx4 & 7) * 4, row = idx4 >> 3;
            float4 v = *(const float4*)(xbase + (size_t)row * (TSTEPS * IDIM) + k0 + k4);
            As[(k4 + 0) * AS_STRIDE + row] = v.x;
            As[(k4 + 1) * AS_STRIDE + row] = v.y;
            As[(k4 + 2) * AS_STRIDE + row] = v.z;
            As[(k4 + 3) * AS_STRIDE + row] = v.w;
        }
        #pragma unroll
        for (int l = 0; l < 4; l++) {
            int idx4 = tid + l * 256;
            int n4 = (idx4 & 31) * 4, k = idx4 >> 5;
            *(float4*)(&Bs[k * 128 + n4]) =
                *(const float4*)(g_Wih_t + (size_t)(k0 + k) * GDIM + n0 + n4);
        }
        __syncthreads();
        #pragma unroll
        for (int k = 0; k < GM_BK; k++) {
            float4 a = *(const float4*)(&As[k * AS_STRIDE + tm * 4]);
            float4 p = *(const float4*)(&Bs[k * 128 + tn8]);
            float4 q = *(const float4*)(&Bs[k * 128 + tn8 + 4]);
            float av[4] = {a.x, a.y, a.z, a.w};
            float bv[8] = {p.x, p.y, p.z, p.w, q.x, q.y, q.z, q.w};
            #pragma unroll
            for (int m = 0; m < 4; m++)
                #pragma unroll
                for (int n = 0; n < 8; n++)
                    acc[m][n] = fmaf(av[m], bv[n], acc[m][n]);
        }
        __syncthreads();
    }
    // transposed epilogue: [t][g'][b]
    #pragma unroll
    for (int n = 0; n < 8; n++) {
        float bz = g_bias[n0 + tn8 + n];
        float4 o = make_float4(acc[0][n] + bz, acc[1][n] + bz,
                               acc[2][n] + bz, acc[3][n] + bz);
        *(float4*)(g_xw + ((size_t)t * GDIM + n0 + tn8 + n) * BATCH + b0 + tm * 4) = o;
    }
}

// --------------------------- recurrent ------------------------------------
// Main role: warp w=(je=w&7, khp=w>>3), lane l=(bo=l>>1, kk=l&1), khid=2khp+kk.
// Thread: 8 b (oct bo) x 4 gates over 64 j (slab je); acc = 16 b-paired f32x2.
// Reduce role: thread (bC=tid&127, khC=tid>>7) sums 8 je-partials per gate.
__global__ __launch_bounds__(512, 1) void lstm_rec(int t0) {
    extern __shared__ float smem[];
    float* sW = smem;            // 16384 floats (64 KB)
    float* P  = smem + 16384;    // 16384 floats (64 KB): [je][khid][g][b]

    const int cta = blockIdx.x, tid = threadIdx.x;
    {
        const float* src = g_W2 + (size_t)cta * 16384;
        for (int p = tid; p < 16384; p += 512)
            sW[p] = src[p];
    }

    const int w = tid >> 5, l = tid & 31;
    const int je = w & 7, khp = w >> 3;
    const int bo = l >> 1, kk = l & 1;
    const int khid = 2 * khp + kk;
    const int jbase = je * 64, bbase = bo * 8;
    const float* wb = sW + jbase * 32 + khid * 8;
    float* Pw = P + ((je * 4 + khid) * 4) * 128 + bbase;

    const int bC = tid & 127, khC = tid >> 7;
    const int cell = bC * HDIM + cta * 4 + khC;
    const float* Pr = P + (khC * 4) * 128 + bC;
    const float* xwb = g_xw + (size_t)(cta * 16 + khC * 4) * BATCH + bC;
    float* hOut = g_hP + (size_t)(cta * 4 + khC) * BATCH + bC;

    float creg = (t0 == 0) ? 0.0f : g_c[cell];
    __syncthreads();

    float xv0, xv1, xv2, xv3;
    {
        const float* xp = xwb + (size_t)t0 * (GDIM * BATCH);
        xv0 = __ldg(xp); xv1 = __ldg(xp + BATCH);
        xv2 = __ldg(xp + 2 * BATCH); xv3 = __ldg(xp + 3 * BATCH);
    }

    for (int tl = 0; tl < REC_CHUNK; tl++) {
        const int t = t0 + tl;
        ull acc[4][4];
        #pragma unroll
        for (int bp = 0; bp < 4; bp++)
            #pragma unroll
            for (int g = 0; g < 4; g++) acc[bp][g] = 0ull;

        if (t > 0) {
            const float* hb = g_hP + (size_t)(t & 1) * HB + (size_t)jbase * BATCH + bbase;
            #pragma unroll 8
            for (int jj = 0; jj < 64; jj++) {
                ulonglong2 u01 = __ldcg((const ulonglong2*)(hb + (size_t)jj * BATCH));
                ulonglong2 u23 = __ldcg((const ulonglong2*)(hb + (size_t)jj * BATCH + 4));
                const float* wj = wb + jj * 32;
                ulonglong2 w01 = *(const ulonglong2*)(wj);       // (g0,g0),(g1,g1)
                ulonglong2 w23 = *(const ulonglong2*)(wj + 4);   // (g2,g2),(g3,g3)
                fma2(acc[0][0], u01.x, w01.x); fma2(acc[0][1], u01.x, w01.y);
                fma2(acc[0][2], u01.x, w23.x); fma2(acc[0][3], u01.x, w23.y);
                fma2(acc[1][0], u01.y, w01.x); fma2(acc[1][1], u01.y, w01.y);
                fma2(acc[1][2], u01.y, w23.x); fma2(acc[1][3], u01.y, w23.y);
                fma2(acc[2][0], u23.x, w01.x); fma2(acc[2][1], u23.x, w01.y);
                fma2(acc[2][2], u23.x, w23.x); fma2(acc[2][3], u23.x, w23.y);
                fma2(acc[3][0], u23.y, w01.x); fma2(acc[3][1], u23.y, w01.y);
                fma2(acc[3][2], u23.y, w23.x); fma2(acc[3][3], u23.y, w23.y);
            }
        }

        #pragma unroll
        for (int g = 0; g < 4; g++) {
            ulonglong2 v;
            v.x = acc[0][g]; v.y = acc[1][g];
            *(ulonglong2*)(Pw + g * 128) = v;
            v.x = acc[2][g]; v.y = acc[3][g];
            *(ulonglong2*)(Pw + g * 128 + 4) = v;
        }
        __syncthreads();

        float s0 = xv0, s1 = xv1, s2 = xv2, s3 = xv3;
        #pragma unroll
        for (int e = 0; e < 8; e++) {
            const float* pp = Pr + e * 2048;
            s0 += pp[0]; s1 += pp[128]; s2 += pp[256]; s3 += pp[384];
        }

        float ig = __fdividef(1.0f, 1.0f + __expf(-s0));
        float fg = __fdividef(1.0f, 1.0f + __expf(-s1));
        float gg = 1.0f - __fdividef(2.0f, __expf(2.0f * s2) + 1.0f);
        float og = __fdividef(1.0f, 1.0f + __expf(-s3));
        creg = fg * creg + ig * gg;
        float th = 1.0f - __fdividef(2.0f, __expf(2.0f * creg) + 1.0f);
        float hv = og * th;

        float* hp = hOut + (size_t)((t + 1) & 1) * HB;
        asm volatile("st.global.cg.f32 [%0], %1;" :: "l"(hp), "f"(hv) : "memory");

        if (tl + 1 < REC_CHUNK) {
            const float* xp = xwb + (size_t)(t + 1) * (GDIM * BATCH);
            xv0 = __ldg(xp); xv1 = __ldg(xp + BATCH);
            xv2 = __ldg(xp + 2 * BATCH); xv3 = __ldg(xp + 3 * BATCH);
        }

        unsigned bar_t = (unsigned)(t + 1) * 128u;
        __syncthreads();
        if (tid == 0) {
            asm volatile("red.release.gpu.global.add.u32 [%0], 1;" :: "l"(&g_bar) : "memory");
            unsigned v;
            do {
                asm volatile("ld.acquire.gpu.global.u32 %0, [%1];" : "=r"(v) : "l"(&g_bar) : "memory");
            } while (v < bar_t);
        }
        __syncthreads();
    }
    g_c[cell] = creg;
}

// ------------------------------- fc ----------------------------------------
__global__ void fc_kernel(const float* __restrict__ fc_w,
                          const float* __restrict__ fc_b,
                          float* __restrict__ out) {
    int b = blockIdx.x, tid = threadIdx.x;     // 128 x 128
    float s = 0.0f;
    for (int j = tid; j < HDIM; j += 128)
        s = fmaf(g_hP[(size_t)j * BATCH + b], fc_w[j], s);
    s += __shfl_down_sync(0xffffffffu, s, 16);
    s += __shfl_down_sync(0xffffffffu, s, 8);
    s += __shfl_down_sync(0xffffffffu, s, 4);
    s += __shfl_down_sync(0xffffffffu, s, 2);
    s += __shfl_down_sync(0xffffffffu, s, 1);
    __shared__ float red[4];
    if ((tid & 31) == 0) red[tid >> 5] = s;
    __syncthreads();
    if (tid == 0) out[b] = red[0] + red[1] + red[2] + red[3] + fc_b[0];
}

// ----------------------------- launcher ------------------------------------
extern "C" void kernel_launch(void* const* d_in, const int* in_sizes, int n_in,
                              void* d_out, int out_size) {
    const float* x    = (const float*)d_in[0];
    const float* W_ih = (const float*)d_in[1];
    const float* W_hh = (const float*)d_in[2];
    const float* b_ih = (const float*)d_in[3];
    const float* b_hh = (const float*)d_in[4];
    const float* fc_w = (const float*)d_in[5];
    const float* fc_b = (const float*)d_in[6];
    float* out = (float*)d_out;

    cudaFuncSetAttribute(lstm_rec, cudaFuncAttributeMaxDynamicSharedMemorySize, 131072);

    init_kernel<<<2048, 256>>>(W_ih, W_hh, b_ih, b_hh);
    dim3 gg(16, 2048);
    xw_gemm<<<gg, 256>>>(x);
    for (int c = 0; c < TSTEPS / REC_CHUNK; c++)
        lstm_rec<<<128, 512, 131072>>>(c * REC_CHUNK);
    fc_kernel<<<128, 128>>>(fc_w, fc_b, out);
}